// round 13
// baseline (speedup 1.0000x reference)
#include <cuda_runtime.h>
#include <cuda_fp16.h>
#include <math.h>

#define NN   50000
#define EE   800000
#define HIDD 128
#define FEE  16
#define BBB  8
#define NEG_SLOPE 0.2f

typedef unsigned long long u64;

// ---------------- scratch (static device memory; doubled for 2-stream overlap) ----
__device__ float  g_xl[2][NN * HIDD];
__device__ float  g_xr[2][NN * HIDD];
__device__ float  g_h [2][NN * HIDD];
__device__ float  g_h2[2][NN * HIDD];
__device__ int    g_deg[2][NN];
__device__ int    g_off[2][NN + 1];
__device__ int    g_cur[2][NN];
__device__ int    g_srcidx[2][EE];
__device__ float  g_eattr[2][EE * FEE];
__device__ __half g_ew[2][(size_t)EE * HIDD];   // per-edge emb (fp16), CSR order
__device__ int    g_bsums[2][1024];
__device__ float    g_psum[2 * BBB * HIDD];
__device__ unsigned g_pmax[2 * BBB * HIDD];
__device__ int      g_pcnt[2 * BBB];

// ---------------- f32x2 packed helpers ----------------
__device__ __forceinline__ u64 pack2(float lo, float hi) {
    u64 r; asm("mov.b64 %0,{%1,%2};" : "=l"(r) : "f"(lo), "f"(hi)); return r;
}
__device__ __forceinline__ u64 splat2(float v) { return pack2(v, v); }
__device__ __forceinline__ u64 ffma2(u64 a, u64 b, u64 c) {
    u64 d; asm("fma.rn.f32x2 %0,%1,%2,%3;" : "=l"(d) : "l"(a), "l"(b), "l"(c)); return d;
}
__device__ __forceinline__ u64 fadd2(u64 a, u64 b) {
    u64 d; asm("add.rn.f32x2 %0,%1,%2;" : "=l"(d) : "l"(a), "l"(b)); return d;
}
__device__ __forceinline__ float2 unpack2(u64 v) {
    float2 f; asm("mov.b64 {%0,%1},%2;" : "=f"(f.x), "=f"(f.y) : "l"(v)); return f;
}

__device__ __forceinline__ unsigned enc_ord(float f) {
    unsigned u = __float_as_uint(f);
    return (u & 0x80000000u) ? ~u : (u | 0x80000000u);
}
__device__ __forceinline__ float dec_ord(unsigned e) {
    return (e & 0x80000000u) ? __uint_as_float(e ^ 0x80000000u) : __uint_as_float(~e);
}

// tf32 round-to-nearest conversion
__device__ __forceinline__ float tf32r(float x) {
    asm("cvt.rna.tf32.f32 %0, %0;" : "+f"(x));
    return x;
}

__device__ __forceinline__ void mma_tf32(float* c,
    unsigned a0, unsigned a1, unsigned a2, unsigned a3,
    unsigned b0, unsigned b1)
{
    asm("mma.sync.aligned.m16n8k8.row.col.f32.tf32.tf32.f32 "
        "{%0,%1,%2,%3}, {%4,%5,%6,%7}, {%8,%9}, {%0,%1,%2,%3};"
        : "+f"(c[0]), "+f"(c[1]), "+f"(c[2]), "+f"(c[3])
        : "r"(a0), "r"(a1), "r"(a2), "r"(a3), "r"(b0), "r"(b1));
}

// ---------------- CSR build ----------------
__global__ void count_kernel(const int* __restrict__ ei, int* __restrict__ deg, int E) {
    int e = blockIdx.x * blockDim.x + threadIdx.x;
    if (e >= E) return;
    atomicAdd(&deg[ei[E + e]], 1);
}

__global__ void partial_kernel(const int* __restrict__ deg, int* __restrict__ bsums, int n) {
    int tid = threadIdx.x;
    int i = blockIdx.x * 1024 + tid;
    int v = (i < n) ? deg[i] : 0;
#pragma unroll
    for (int o = 16; o; o >>= 1) v += __shfl_xor_sync(0xffffffffu, v, o);
    __shared__ int ws[32];
    if ((tid & 31) == 0) ws[tid >> 5] = v;
    __syncthreads();
    if (tid < 32) {
        int s = ws[tid];
#pragma unroll
        for (int o = 16; o; o >>= 1) s += __shfl_xor_sync(0xffffffffu, s, o);
        if (tid == 0) bsums[blockIdx.x] = s;
    }
}

__global__ void scan_bsums_kernel(int* __restrict__ bsums, int nb,
                                  int* __restrict__ off, int n) {
    int tid = threadIdx.x;
    int lane = tid & 31, wid = tid >> 5;
    int v = (tid < nb) ? bsums[tid] : 0;
    int x = v;
#pragma unroll
    for (int o = 1; o < 32; o <<= 1) {
        int t = __shfl_up_sync(0xffffffffu, x, o);
        if (lane >= o) x += t;
    }
    __shared__ int ws[32];
    if (lane == 31) ws[wid] = x;
    __syncthreads();
    if (wid == 0) {
        int s = ws[lane];
#pragma unroll
        for (int o = 1; o < 32; o <<= 1) {
            int t = __shfl_up_sync(0xffffffffu, s, o);
            if (lane >= o) s += t;
        }
        ws[lane] = s;
    }
    __syncthreads();
    int incl = (wid ? ws[wid - 1] : 0) + x;
    if (tid < nb) bsums[tid] = incl - v;
    if (tid == nb - 1) off[n] = incl;
}

__global__ void write_off_kernel(const int* __restrict__ deg, const int* __restrict__ bscan,
                                 int* __restrict__ off, int* __restrict__ cur, int n) {
    int tid = threadIdx.x;
    int i = blockIdx.x * 1024 + tid;
    int lane = tid & 31, wid = tid >> 5;
    int v = (i < n) ? deg[i] : 0;
    int x = v;
#pragma unroll
    for (int o = 1; o < 32; o <<= 1) {
        int t = __shfl_up_sync(0xffffffffu, x, o);
        if (lane >= o) x += t;
    }
    __shared__ int ws[32];
    if (lane == 31) ws[wid] = x;
    __syncthreads();
    if (wid == 0) {
        int s = ws[lane];
#pragma unroll
        for (int o = 1; o < 32; o <<= 1) {
            int t = __shfl_up_sync(0xffffffffu, s, o);
            if (lane >= o) s += t;
        }
        ws[lane] = s;
    }
    __syncthreads();
    int excl = bscan[blockIdx.x] + (wid ? ws[wid - 1] : 0) + x - v;
    if (i < n) { off[i] = excl; cur[i] = excl; }
}

__global__ void scatter_kernel(const int* __restrict__ ei, const float* __restrict__ eattr_in,
                               int* __restrict__ cur, int* __restrict__ csr_src,
                               float* __restrict__ eattr_out, int E) {
    int e = blockIdx.x * blockDim.x + threadIdx.x;
    if (e >= E) return;
    int src = ei[e];
    int dst = ei[E + e];
    int pos = atomicAdd(&cur[dst], 1);
    csr_src[pos] = src;
    const float4* s = (const float4*)&eattr_in[(size_t)e * FEE];
    float4* d = (float4*)&eattr_out[(size_t)pos * FEE];
    d[0] = s[0]; d[1] = s[1]; d[2] = s[2]; d[3] = s[3];
}

// ---------------- tf32 tensor-core dual node GEMM ----------------
__global__ __launch_bounds__(256) void gemm_tc_kernel(
    const float* __restrict__ A,
    const float* __restrict__ Wl, const float* __restrict__ bl, float* __restrict__ outl,
    const float* __restrict__ Wr, const float* __restrict__ br, float* __restrict__ outr,
    int nrows)
{
    __shared__ float Wsm[128][72];
    __shared__ float Asm[128][20];

    int tid = threadIdx.x;
    int which = blockIdx.x >> 1;
    const float* W    = which ? Wr : Wl;
    const float* bias = which ? br : bl;
    float*       out  = which ? outr : outl;
    int row0 = blockIdx.y * 128;
    int col0 = (blockIdx.x & 1) * 64;
    int warp = tid >> 5, lane = tid & 31;
    int lr = lane >> 2;
    int lc = lane & 3;

    for (int i = tid; i < 128 * 16; i += 256) {
        int k  = i >> 4;
        int c4 = (i & 15) << 2;
        float4 w = *(const float4*)&W[(size_t)k * 128 + col0 + c4];
        Wsm[k][c4 + 0] = tf32r(w.x);
        Wsm[k][c4 + 1] = tf32r(w.y);
        Wsm[k][c4 + 2] = tf32r(w.z);
        Wsm[k][c4 + 3] = tf32r(w.w);
    }

    float acc[8][4];
#pragma unroll
    for (int t = 0; t < 8; t++)
#pragma unroll
        for (int j = 0; j < 4; j++) acc[t][j] = 0.f;

    float4 pre[2];
    auto loadA = [&](int k0) {
#pragma unroll
        for (int i = 0; i < 2; i++) {
            int idx = tid + 256 * i;
            int r  = idx >> 2;
            int c4 = (idx & 3) << 2;
            int grow = row0 + r;
            pre[i] = (grow < nrows) ? *(const float4*)&A[(size_t)grow * 128 + k0 + c4]
                                    : make_float4(0.f, 0.f, 0.f, 0.f);
        }
    };
    auto storeA = [&]() {
#pragma unroll
        for (int i = 0; i < 2; i++) {
            int idx = tid + 256 * i;
            int r  = idx >> 2;
            int c4 = (idx & 3) << 2;
            Asm[r][c4 + 0] = tf32r(pre[i].x);
            Asm[r][c4 + 1] = tf32r(pre[i].y);
            Asm[r][c4 + 2] = tf32r(pre[i].z);
            Asm[r][c4 + 3] = tf32r(pre[i].w);
        }
    };

    loadA(0);
    storeA();
    __syncthreads();

#pragma unroll
    for (int ch = 0; ch < 8; ch++) {
        if (ch < 7) loadA((ch + 1) * 16);
#pragma unroll
        for (int ks = 0; ks < 2; ks++) {
            int kk = ks * 8;
            int kg = ch * 16 + kk;
            unsigned a0 = __float_as_uint(Asm[warp * 16 + lr    ][kk + lc    ]);
            unsigned a1 = __float_as_uint(Asm[warp * 16 + lr + 8][kk + lc    ]);
            unsigned a2 = __float_as_uint(Asm[warp * 16 + lr    ][kk + lc + 4]);
            unsigned a3 = __float_as_uint(Asm[warp * 16 + lr + 8][kk + lc + 4]);
#pragma unroll
            for (int nt = 0; nt < 8; nt++) {
                unsigned b0 = __float_as_uint(Wsm[kg + lc    ][nt * 8 + lr]);
                unsigned b1 = __float_as_uint(Wsm[kg + lc + 4][nt * 8 + lr]);
                mma_tf32(acc[nt], a0, a1, a2, a3, b0, b1);
            }
        }
        __syncthreads();
        if (ch < 7) { storeA(); __syncthreads(); }
    }

    int r0 = row0 + warp * 16 + lr;
    int r1 = r0 + 8;
#pragma unroll
    for (int nt = 0; nt < 8; nt++) {
        int c = col0 + nt * 8 + 2 * lc;
        float bv0 = bias[c], bv1 = bias[c + 1];
        if (r0 < nrows) {
            float2 o = make_float2(acc[nt][0] + bv0, acc[nt][1] + bv1);
            *(float2*)&out[(size_t)r0 * 128 + c] = o;
        }
        if (r1 < nrows) {
            float2 o = make_float2(acc[nt][2] + bv0, acc[nt][3] + bv1);
            *(float2*)&out[(size_t)r1 * 128 + c] = o;
        }
    }
}

// ---------------- edge-embedding GEMM: ew[e][128] = eattr[e][0:16] @ We ----------
// Streaming compute kernel (no dependent gathers). Warp per 4 edges, grid-stride.
// Output fp16 (half), CSR edge order. Lane layout matches edge_kernel (ch).
__global__ __launch_bounds__(128) void ewgemm_kernel(
    const float* __restrict__ eattr, const float* __restrict__ We,
    __half* __restrict__ ew, int E)
{
    __shared__ __align__(16) float sWe[16][128];
    for (int i = threadIdx.x; i < 16 * 128 / 4; i += 128)
        *(float4*)&sWe[0][i * 4] = *(const float4*)&We[i * 4];
    __syncthreads();

    int lane = threadIdx.x & 31;
    int wg   = (blockIdx.x * blockDim.x + threadIdx.x) >> 5;
    int nw   = (gridDim.x * blockDim.x) >> 5;
    int ch = ((lane >> 3) << 5) + ((lane & 7) << 2);

    for (int i0 = wg * 4; i0 < E; i0 += nw * 4) {
        u64 m0[4], m1[4];
#pragma unroll
        for (int j = 0; j < 4; j++) { m0[j] = 0ull; m1[j] = 0ull; }
        int eidx[4];
#pragma unroll
        for (int j = 0; j < 4; j++) eidx[j] = min(i0 + j, E - 1);

#pragma unroll
        for (int kk = 0; kk < 4; kk++) {
            float4 ea[4];
#pragma unroll
            for (int j = 0; j < 4; j++)
                ea[j] = *(const float4*)&eattr[(size_t)eidx[j] * FEE + kk * 4];
#pragma unroll
            for (int r = 0; r < 4; r++) {
                ulonglong2 w = *(const ulonglong2*)&sWe[4 * kk + r][ch];
#pragma unroll
                for (int j = 0; j < 4; j++) {
                    float ev = (r == 0) ? ea[j].x : (r == 1) ? ea[j].y
                             : (r == 2) ? ea[j].z : ea[j].w;
                    u64 sv = splat2(ev);
                    m0[j] = ffma2(sv, w.x, m0[j]);
                    m1[j] = ffma2(sv, w.y, m1[j]);
                }
            }
        }
#pragma unroll
        for (int j = 0; j < 4; j++) {
            if (i0 + j >= E) break;
            float2 f0 = unpack2(m0[j]), f1 = unpack2(m1[j]);
            __half2 h0 = __floats2half2_rn(f0.x, f0.y);
            __half2 h1 = __floats2half2_rn(f1.x, f1.y);
            uint2 pk;
            pk.x = *(unsigned*)&h0;
            pk.y = *(unsigned*)&h1;
            *(uint2*)&ew[(size_t)eidx[j] * HIDD + ch] = pk;
        }
    }
}

// ---------------- fused GATv2 edge pass (lean: ew precomputed) ----------------
__global__ __launch_bounds__(128) void edge_kernel(
    const float* __restrict__ xl, const float* __restrict__ xr,
    const __half* __restrict__ ew, const int* __restrict__ csr_src,
    const int* __restrict__ off,
    const float* __restrict__ att, const float* __restrict__ bias,
    float* __restrict__ out, int n_nodes)
{
    int lane = threadIdx.x & 31;
    int wg   = (blockIdx.x * blockDim.x + threadIdx.x) >> 5;
    int nw   = (gridDim.x * blockDim.x) >> 5;
    int ch = ((lane >> 3) << 5) + ((lane & 7) << 2);   // head = lane/8, 4 ch each

    float4 att4 = *(const float4*)&att[ch];
    float4 b4   = *(const float4*)&bias[ch];

    for (int node = wg; node < n_nodes; node += nw) {
        int s = off[node], e = off[node + 1];
        ulonglong2 xrp = *(const ulonglong2*)&xr[(size_t)node * 128 + ch];
        u64 acc0 = 0ull, acc1 = 0ull;
        float denom = 0.f;

        for (int i = s; i < e; i += 4) {
            int pidx[4];
#pragma unroll
            for (int j = 0; j < 4; j++) pidx[j] = min(i + j, e - 1);
            int sidx[4];
#pragma unroll
            for (int j = 0; j < 4; j++) sidx[j] = __ldg(&csr_src[pidx[j]]);
            ulonglong2 xlv[4];
#pragma unroll
            for (int j = 0; j < 4; j++)
                xlv[j] = *(const ulonglong2*)&xl[(size_t)sidx[j] * 128 + ch];
            uint2 wv[4];
#pragma unroll
            for (int j = 0; j < 4; j++)
                wv[j] = *(const uint2*)&ew[(size_t)pidx[j] * HIDD + ch];

            float pv[4];
#pragma unroll
            for (int j = 0; j < 4; j++) {
                float2 g0 = __half22float2(*(__half2*)&wv[j].x);
                float2 g1 = __half22float2(*(__half2*)&wv[j].y);
                u64 m0 = fadd2(fadd2(xlv[j].x, xrp.x), pack2(g0.x, g0.y));
                u64 m1 = fadd2(fadd2(xlv[j].y, xrp.y), pack2(g1.x, g1.y));
                float2 f0 = unpack2(m0), f1 = unpack2(m1);
                pv[j] = fmaxf(f0.x, NEG_SLOPE * f0.x) * att4.x
                      + fmaxf(f0.y, NEG_SLOPE * f0.y) * att4.y
                      + fmaxf(f1.x, NEG_SLOPE * f1.x) * att4.z
                      + fmaxf(f1.y, NEG_SLOPE * f1.y) * att4.w;
            }
#pragma unroll
            for (int o = 1; o <= 4; o <<= 1) {
#pragma unroll
                for (int j = 0; j < 4; j++)
                    pv[j] += __shfl_xor_sync(0xffffffffu, pv[j], o);
            }
#pragma unroll
            for (int j = 0; j < 4; j++) {
                float ex = __expf(pv[j]);
                if (i + j < e) {            // warp-uniform predicate
                    denom += ex;
                    u64 e2 = splat2(ex);
                    acc0 = ffma2(e2, xlv[j].x, acc0);
                    acc1 = ffma2(e2, xlv[j].y, acc1);
                }
            }
        }

        float inv = 1.f / (denom + 1e-16f);
        float2 a0 = unpack2(acc0), a1 = unpack2(acc1);
        float ox = a0.x * inv + b4.x;
        float oy = a0.y * inv + b4.y;
        float oz = a1.x * inv + b4.z;
        float ow = a1.y * inv + b4.w;
        float4 o;
        o.x = (ox > 0.f) ? ox : expm1f(ox);
        o.y = (oy > 0.f) ? oy : expm1f(oy);
        o.z = (oz > 0.f) ? oz : expm1f(oz);
        o.w = (ow > 0.f) ? ow : expm1f(ow);
        *(float4*)&out[(size_t)node * 128 + ch] = o;
    }
}

// ---------------- batch pooling ----------------
__global__ __launch_bounds__(128) void pool_kernel(
    const float* __restrict__ h, const int* __restrict__ batch,
    float* __restrict__ gsum, unsigned* __restrict__ gmax, int* __restrict__ gcnt,
    int n_nodes)
{
    __shared__ float    ssum[BBB][HIDD];
    __shared__ unsigned smax[BBB][HIDD];
    __shared__ int      scnt[BBB];
    int tid = threadIdx.x;
#pragma unroll
    for (int b = 0; b < BBB; b++) { ssum[b][tid] = 0.f; smax[b][tid] = 0u; }
    if (tid < BBB) scnt[tid] = 0;
    __syncthreads();
    int chunk = (n_nodes + gridDim.x - 1) / gridDim.x;
    int st = blockIdx.x * chunk;
    int en = min(st + chunk, n_nodes);
    for (int n = st; n < en; n++) {
        int b = __ldg(&batch[n]);
        float v = h[(size_t)n * 128 + tid];
        ssum[b][tid] += v;
        unsigned ev = enc_ord(v);
        if (ev > smax[b][tid]) smax[b][tid] = ev;
        if (tid == 0) scnt[b]++;
    }
    __syncthreads();
#pragma unroll
    for (int b = 0; b < BBB; b++) {
        atomicAdd(&gsum[b * HIDD + tid], ssum[b][tid]);
        atomicMax(&gmax[b * HIDD + tid], smax[b][tid]);
    }
    if (tid < BBB) atomicAdd(&gcnt[tid], scnt[tid]);
}

// ---------------- FC head ----------------
__global__ __launch_bounds__(128) void fc_kernel(
    const float* __restrict__ gsum, const unsigned* __restrict__ gmax,
    const int* __restrict__ gcnt,
    const float* __restrict__ Wf1, const float* __restrict__ bf1,
    const float* __restrict__ Wf2, const float* __restrict__ bf2,
    float* __restrict__ out)
{
    __shared__ float comb[512];
    __shared__ float hid[128];
    int b = blockIdx.x;
    int tid = threadIdx.x;
#pragma unroll
    for (int g = 0; g < 2; g++) {
        int cnt = gcnt[g * BBB + b];
        float invc = 1.f / (float)max(cnt, 1);
        float mean = gsum[(size_t)(g * BBB + b) * HIDD + tid] * invc;
        unsigned mu = gmax[(size_t)(g * BBB + b) * HIDD + tid];
        float mx = (cnt > 0) ? dec_ord(mu) : 0.f;
        comb[g * 256 + tid]       = mean;
        comb[g * 256 + 128 + tid] = mx;
    }
    __syncthreads();
    float a = bf1[tid];
#pragma unroll 8
    for (int i = 0; i < 512; i++) a += comb[i] * Wf1[(size_t)i * 128 + tid];
    hid[tid] = fmaxf(a, 0.f);
    __syncthreads();
    if (tid < 32) {
        float s = 0.f;
        for (int j = tid; j < 128; j += 32) s += hid[j] * Wf2[j];
        s += __shfl_xor_sync(0xffffffffu, s, 1);
        s += __shfl_xor_sync(0xffffffffu, s, 2);
        s += __shfl_xor_sync(0xffffffffu, s, 4);
        s += __shfl_xor_sync(0xffffffffu, s, 8);
        s += __shfl_xor_sync(0xffffffffu, s, 16);
        if (tid == 0) out[b] = 1.f / (1.f + __expf(-(s + bf2[0])));
    }
}

// ---------------- launch ----------------
extern "C" void kernel_launch(void* const* d_in, const int* in_sizes, int n_in,
                              void* d_out, int out_size)
{
    (void)n_in; (void)out_size;
    int n = in_sizes[3];
    int E = in_sizes[1] / 2;

    static cudaStream_t s2 = 0;
    static cudaEvent_t evF = 0, evJ = 0;
    if (!s2) {
        cudaStreamCreateWithFlags(&s2, cudaStreamNonBlocking);
        cudaEventCreateWithFlags(&evF, cudaEventDisableTiming);
        cudaEventCreateWithFlags(&evJ, cudaEventDisableTiming);
    }

    void* p;
    float *xl, *xr, *h, *h2, *eattr, *psum;
    __half *ew;
    int *deg, *off, *cur, *srcb, *pcnt, *bsums;
    unsigned *pmax;
    cudaGetSymbolAddress(&p, g_xl);     xl    = (float*)p;
    cudaGetSymbolAddress(&p, g_xr);     xr    = (float*)p;
    cudaGetSymbolAddress(&p, g_h);      h     = (float*)p;
    cudaGetSymbolAddress(&p, g_h2);     h2    = (float*)p;
    cudaGetSymbolAddress(&p, g_deg);    deg   = (int*)p;
    cudaGetSymbolAddress(&p, g_off);    off   = (int*)p;
    cudaGetSymbolAddress(&p, g_cur);    cur   = (int*)p;
    cudaGetSymbolAddress(&p, g_srcidx); srcb  = (int*)p;
    cudaGetSymbolAddress(&p, g_eattr);  eattr = (float*)p;
    cudaGetSymbolAddress(&p, g_ew);     ew    = (__half*)p;
    cudaGetSymbolAddress(&p, g_bsums);  bsums = (int*)p;
    cudaGetSymbolAddress(&p, g_psum);   psum  = (float*)p;
    cudaGetSymbolAddress(&p, g_pmax);   pmax  = (unsigned*)p;
    cudaGetSymbolAddress(&p, g_pcnt);   pcnt  = (int*)p;

    const float* W1l  = (const float*)d_in[8];
    const float* b1l  = (const float*)d_in[9];
    const float* W1r  = (const float*)d_in[10];
    const float* b1r  = (const float*)d_in[11];
    const float* W1e  = (const float*)d_in[12];
    const float* att1 = (const float*)d_in[13];
    const float* bias1= (const float*)d_in[14];
    const float* W2l  = (const float*)d_in[15];
    const float* b2l  = (const float*)d_in[16];
    const float* W2r  = (const float*)d_in[17];
    const float* b2r  = (const float*)d_in[18];
    const float* W2e  = (const float*)d_in[19];
    const float* att2 = (const float*)d_in[20];
    const float* bias2= (const float*)d_in[21];
    const float* Wf1  = (const float*)d_in[22];
    const float* bf1  = (const float*)d_in[23];
    const float* Wf2  = (const float*)d_in[24];
    const float* bf2  = (const float*)d_in[25];

    cudaMemsetAsync(psum, 0, 2 * BBB * HIDD * sizeof(float), 0);
    cudaMemsetAsync(pmax, 0, 2 * BBB * HIDD * sizeof(unsigned), 0);
    cudaMemsetAsync(pcnt, 0, 2 * BBB * sizeof(int), 0);

    cudaEventRecord(evF, 0);
    cudaStreamWaitEvent(s2, evF, 0);

    dim3 ggrid(4, (n + 127) / 128);
    int eblocks = (E + 255) / 256;
    int nb1024 = (n + 1023) / 1024;
    int edge_blocks = 1184;

    for (int g = 0; g < 2; g++) {
        cudaStream_t st = (g == 0) ? (cudaStream_t)0 : s2;
        const float* x     = (const float*)d_in[g * 4 + 0];
        const int*   ei    = (const int*)  d_in[g * 4 + 1];
        const float* ea    = (const float*)d_in[g * 4 + 2];
        const int*   batch = (const int*)  d_in[g * 4 + 3];
        float* xl_g    = xl    + (size_t)g * NN * HIDD;
        float* xr_g    = xr    + (size_t)g * NN * HIDD;
        float* h_g     = h     + (size_t)g * NN * HIDD;
        float* h2_g    = h2    + (size_t)g * NN * HIDD;
        int*   deg_g   = deg   + (size_t)g * NN;
        int*   off_g   = off   + (size_t)g * (NN + 1);
        int*   cur_g   = cur   + (size_t)g * NN;
        int*   src_g   = srcb  + (size_t)g * EE;
        float* eattr_g = eattr + (size_t)g * EE * FEE;
        __half* ew_g   = ew    + (size_t)g * EE * HIDD;
        int*   bs_g    = bsums + (size_t)g * 1024;

        cudaMemsetAsync(deg_g, 0, n * sizeof(int), st);
        count_kernel<<<eblocks, 256, 0, st>>>(ei, deg_g, E);
        partial_kernel<<<nb1024, 1024, 0, st>>>(deg_g, bs_g, n);
        scan_bsums_kernel<<<1, 1024, 0, st>>>(bs_g, nb1024, off_g, n);
        write_off_kernel<<<nb1024, 1024, 0, st>>>(deg_g, bs_g, off_g, cur_g, n);
        scatter_kernel<<<eblocks, 256, 0, st>>>(ei, ea, cur_g, src_g, eattr_g, E);

        // layer 1
        gemm_tc_kernel<<<ggrid, 256, 0, st>>>(x, W1l, b1l, xl_g, W1r, b1r, xr_g, n);
        ewgemm_kernel<<<edge_blocks, 128, 0, st>>>(eattr_g, W1e, ew_g, E);
        edge_kernel<<<edge_blocks, 128, 0, st>>>(xl_g, xr_g, ew_g, src_g, off_g,
                                                 att1, bias1, h_g, n);
        // layer 2
        gemm_tc_kernel<<<ggrid, 256, 0, st>>>(h_g, W2l, b2l, xl_g, W2r, b2r, xr_g, n);
        ewgemm_kernel<<<edge_blocks, 128, 0, st>>>(eattr_g, W2e, ew_g, E);
        edge_kernel<<<edge_blocks, 128, 0, st>>>(xl_g, xr_g, ew_g, src_g, off_g,
                                                 att2, bias2, h2_g, n);

        pool_kernel<<<200, 128, 0, st>>>(h2_g, batch, psum + g * BBB * HIDD,
                                         pmax + g * BBB * HIDD, pcnt + g * BBB, n);
    }

    cudaEventRecord(evJ, s2);
    cudaStreamWaitEvent((cudaStream_t)0, evJ, 0);

    fc_kernel<<<BBB, 128>>>(psum, pmax, pcnt, Wf1, bf1, Wf2, bf2, (float*)d_out);
}

// round 17
// speedup vs baseline: 1.1145x; 1.1145x over previous
#include <cuda_runtime.h>
#include <math.h>

#define NN   50000
#define EE   800000
#define HIDD 128
#define FEE  16
#define BBB  8
#define NEG_SLOPE 0.2f

typedef unsigned long long u64;

// ---------------- scratch (static device memory; doubled for 2-stream overlap) ----
__device__ float g_xl[2][NN * HIDD];
__device__ float g_xr[2][NN * HIDD];
__device__ float g_h [2][NN * HIDD];
__device__ float g_h2[2][NN * HIDD];
__device__ int   g_deg[2][NN];
__device__ int   g_off[2][NN + 1];
__device__ int   g_cur[2][NN];
__device__ int   g_srcidx[2][EE];
__device__ float g_eattr[2][EE * FEE];
__device__ int   g_bsums[2][1024];
__device__ float    g_psum[2 * BBB * HIDD];
__device__ unsigned g_pmax[2 * BBB * HIDD];
__device__ int      g_pcnt[2 * BBB];

// ---------------- f32x2 packed helpers ----------------
__device__ __forceinline__ u64 pack2(float lo, float hi) {
    u64 r; asm("mov.b64 %0,{%1,%2};" : "=l"(r) : "f"(lo), "f"(hi)); return r;
}
__device__ __forceinline__ u64 splat2(float v) { return pack2(v, v); }
__device__ __forceinline__ u64 ffma2(u64 a, u64 b, u64 c) {
    u64 d; asm("fma.rn.f32x2 %0,%1,%2,%3;" : "=l"(d) : "l"(a), "l"(b), "l"(c)); return d;
}
__device__ __forceinline__ u64 fadd2(u64 a, u64 b) {
    u64 d; asm("add.rn.f32x2 %0,%1,%2;" : "=l"(d) : "l"(a), "l"(b)); return d;
}
__device__ __forceinline__ float2 unpack2(u64 v) {
    float2 f; asm("mov.b64 {%0,%1},%2;" : "=f"(f.x), "=f"(f.y) : "l"(v)); return f;
}

__device__ __forceinline__ unsigned enc_ord(float f) {
    unsigned u = __float_as_uint(f);
    return (u & 0x80000000u) ? ~u : (u | 0x80000000u);
}
__device__ __forceinline__ float dec_ord(unsigned e) {
    return (e & 0x80000000u) ? __uint_as_float(e ^ 0x80000000u) : __uint_as_float(~e);
}

// tf32 round-to-nearest conversion
__device__ __forceinline__ float tf32r(float x) {
    asm("cvt.rna.tf32.f32 %0, %0;" : "+f"(x));
    return x;
}

__device__ __forceinline__ void mma_tf32(float* c,
    unsigned a0, unsigned a1, unsigned a2, unsigned a3,
    unsigned b0, unsigned b1)
{
    asm("mma.sync.aligned.m16n8k8.row.col.f32.tf32.tf32.f32 "
        "{%0,%1,%2,%3}, {%4,%5,%6,%7}, {%8,%9}, {%0,%1,%2,%3};"
        : "+f"(c[0]), "+f"(c[1]), "+f"(c[2]), "+f"(c[3])
        : "r"(a0), "r"(a1), "r"(a2), "r"(a3), "r"(b0), "r"(b1));
}

// ---------------- CSR build ----------------
__global__ void count_kernel(const int* __restrict__ ei, int* __restrict__ deg, int E) {
    int e = blockIdx.x * blockDim.x + threadIdx.x;
    if (e >= E) return;
    atomicAdd(&deg[ei[E + e]], 1);
}

__global__ void partial_kernel(const int* __restrict__ deg, int* __restrict__ bsums, int n) {
    int tid = threadIdx.x;
    int i = blockIdx.x * 1024 + tid;
    int v = (i < n) ? deg[i] : 0;
#pragma unroll
    for (int o = 16; o; o >>= 1) v += __shfl_xor_sync(0xffffffffu, v, o);
    __shared__ int ws[32];
    if ((tid & 31) == 0) ws[tid >> 5] = v;
    __syncthreads();
    if (tid < 32) {
        int s = ws[tid];
#pragma unroll
        for (int o = 16; o; o >>= 1) s += __shfl_xor_sync(0xffffffffu, s, o);
        if (tid == 0) bsums[blockIdx.x] = s;
    }
}

__global__ void scan_bsums_kernel(int* __restrict__ bsums, int nb,
                                  int* __restrict__ off, int n) {
    int tid = threadIdx.x;
    int lane = tid & 31, wid = tid >> 5;
    int v = (tid < nb) ? bsums[tid] : 0;
    int x = v;
#pragma unroll
    for (int o = 1; o < 32; o <<= 1) {
        int t = __shfl_up_sync(0xffffffffu, x, o);
        if (lane >= o) x += t;
    }
    __shared__ int ws[32];
    if (lane == 31) ws[wid] = x;
    __syncthreads();
    if (wid == 0) {
        int s = ws[lane];
#pragma unroll
        for (int o = 1; o < 32; o <<= 1) {
            int t = __shfl_up_sync(0xffffffffu, s, o);
            if (lane >= o) s += t;
        }
        ws[lane] = s;
    }
    __syncthreads();
    int incl = (wid ? ws[wid - 1] : 0) + x;
    if (tid < nb) bsums[tid] = incl - v;
    if (tid == nb - 1) off[n] = incl;
}

__global__ void write_off_kernel(const int* __restrict__ deg, const int* __restrict__ bscan,
                                 int* __restrict__ off, int* __restrict__ cur, int n) {
    int tid = threadIdx.x;
    int i = blockIdx.x * 1024 + tid;
    int lane = tid & 31, wid = tid >> 5;
    int v = (i < n) ? deg[i] : 0;
    int x = v;
#pragma unroll
    for (int o = 1; o < 32; o <<= 1) {
        int t = __shfl_up_sync(0xffffffffu, x, o);
        if (lane >= o) x += t;
    }
    __shared__ int ws[32];
    if (lane == 31) ws[wid] = x;
    __syncthreads();
    if (wid == 0) {
        int s = ws[lane];
#pragma unroll
        for (int o = 1; o < 32; o <<= 1) {
            int t = __shfl_up_sync(0xffffffffu, s, o);
            if (lane >= o) s += t;
        }
        ws[lane] = s;
    }
    __syncthreads();
    int excl = bscan[blockIdx.x] + (wid ? ws[wid - 1] : 0) + x - v;
    if (i < n) { off[i] = excl; cur[i] = excl; }
}

__global__ void scatter_kernel(const int* __restrict__ ei, const float* __restrict__ eattr_in,
                               int* __restrict__ cur, int* __restrict__ csr_src,
                               float* __restrict__ eattr_out, int E) {
    int e = blockIdx.x * blockDim.x + threadIdx.x;
    if (e >= E) return;
    int src = ei[e];
    int dst = ei[E + e];
    int pos = atomicAdd(&cur[dst], 1);
    csr_src[pos] = src;
    const float4* s = (const float4*)&eattr_in[(size_t)e * FEE];
    float4* d = (float4*)&eattr_out[(size_t)pos * FEE];
    d[0] = s[0]; d[1] = s[1]; d[2] = s[2]; d[3] = s[3];
}

// ---------------- tf32 tensor-core dual node GEMM ----------------
__global__ __launch_bounds__(256) void gemm_tc_kernel(
    const float* __restrict__ A,
    const float* __restrict__ Wl, const float* __restrict__ bl, float* __restrict__ outl,
    const float* __restrict__ Wr, const float* __restrict__ br, float* __restrict__ outr,
    int nrows)
{
    __shared__ float Wsm[128][72];
    __shared__ float Asm[128][20];

    int tid = threadIdx.x;
    int which = blockIdx.x >> 1;
    const float* W    = which ? Wr : Wl;
    const float* bias = which ? br : bl;
    float*       out  = which ? outr : outl;
    int row0 = blockIdx.y * 128;
    int col0 = (blockIdx.x & 1) * 64;
    int warp = tid >> 5, lane = tid & 31;
    int lr = lane >> 2;
    int lc = lane & 3;

    for (int i = tid; i < 128 * 16; i += 256) {
        int k  = i >> 4;
        int c4 = (i & 15) << 2;
        float4 w = *(const float4*)&W[(size_t)k * 128 + col0 + c4];
        Wsm[k][c4 + 0] = tf32r(w.x);
        Wsm[k][c4 + 1] = tf32r(w.y);
        Wsm[k][c4 + 2] = tf32r(w.z);
        Wsm[k][c4 + 3] = tf32r(w.w);
    }

    float acc[8][4];
#pragma unroll
    for (int t = 0; t < 8; t++)
#pragma unroll
        for (int j = 0; j < 4; j++) acc[t][j] = 0.f;

    float4 pre[2];
    auto loadA = [&](int k0) {
#pragma unroll
        for (int i = 0; i < 2; i++) {
            int idx = tid + 256 * i;
            int r  = idx >> 2;
            int c4 = (idx & 3) << 2;
            int grow = row0 + r;
            pre[i] = (grow < nrows) ? *(const float4*)&A[(size_t)grow * 128 + k0 + c4]
                                    : make_float4(0.f, 0.f, 0.f, 0.f);
        }
    };
    auto storeA = [&]() {
#pragma unroll
        for (int i = 0; i < 2; i++) {
            int idx = tid + 256 * i;
            int r  = idx >> 2;
            int c4 = (idx & 3) << 2;
            Asm[r][c4 + 0] = tf32r(pre[i].x);
            Asm[r][c4 + 1] = tf32r(pre[i].y);
            Asm[r][c4 + 2] = tf32r(pre[i].z);
            Asm[r][c4 + 3] = tf32r(pre[i].w);
        }
    };

    loadA(0);
    storeA();
    __syncthreads();

#pragma unroll
    for (int ch = 0; ch < 8; ch++) {
        if (ch < 7) loadA((ch + 1) * 16);
#pragma unroll
        for (int ks = 0; ks < 2; ks++) {
            int kk = ks * 8;
            int kg = ch * 16 + kk;
            unsigned a0 = __float_as_uint(Asm[warp * 16 + lr    ][kk + lc    ]);
            unsigned a1 = __float_as_uint(Asm[warp * 16 + lr + 8][kk + lc    ]);
            unsigned a2 = __float_as_uint(Asm[warp * 16 + lr    ][kk + lc + 4]);
            unsigned a3 = __float_as_uint(Asm[warp * 16 + lr + 8][kk + lc + 4]);
#pragma unroll
            for (int nt = 0; nt < 8; nt++) {
                unsigned b0 = __float_as_uint(Wsm[kg + lc    ][nt * 8 + lr]);
                unsigned b1 = __float_as_uint(Wsm[kg + lc + 4][nt * 8 + lr]);
                mma_tf32(acc[nt], a0, a1, a2, a3, b0, b1);
            }
        }
        __syncthreads();
        if (ch < 7) { storeA(); __syncthreads(); }
    }

    int r0 = row0 + warp * 16 + lr;
    int r1 = r0 + 8;
#pragma unroll
    for (int nt = 0; nt < 8; nt++) {
        int c = col0 + nt * 8 + 2 * lc;
        float bv0 = bias[c], bv1 = bias[c + 1];
        if (r0 < nrows) {
            float2 o = make_float2(acc[nt][0] + bv0, acc[nt][1] + bv1);
            *(float2*)&out[(size_t)r0 * 128 + c] = o;
        }
        if (r1 < nrows) {
            float2 o = make_float2(acc[nt][2] + bv0, acc[nt][3] + bv1);
            *(float2*)&out[(size_t)r1 * 128 + c] = o;
        }
    }
}

// ---------------- fused GATv2 edge pass (unroll-4, smem W_e, idx prefetch) -------
// The csr_src indices for iteration i+1 are loaded during iteration i, cutting
// the dependent chain from idx(L2)->xl(L2) to just the xl gather per iteration.
__global__ __launch_bounds__(128) void edge_kernel(
    const float* __restrict__ xl, const float* __restrict__ xr,
    const float* __restrict__ eattr, const int* __restrict__ csr_src,
    const int* __restrict__ off, const float* __restrict__ We,
    const float* __restrict__ att, const float* __restrict__ bias,
    float* __restrict__ out, int n_nodes)
{
    __shared__ __align__(16) float sWe[16][128];   // 8 KB
    for (int i = threadIdx.x; i < 16 * 128 / 4; i += 128)
        *(float4*)&sWe[0][i * 4] = *(const float4*)&We[i * 4];
    __syncthreads();

    int lane = threadIdx.x & 31;
    int wg   = (blockIdx.x * blockDim.x + threadIdx.x) >> 5;
    int nw   = (gridDim.x * blockDim.x) >> 5;
    int ch = ((lane >> 3) << 5) + ((lane & 7) << 2);   // head = lane/8, 4 ch each

    float4 att4 = *(const float4*)&att[ch];
    float4 b4   = *(const float4*)&bias[ch];

    for (int node = wg; node < n_nodes; node += nw) {
        int s = off[node], e = off[node + 1];
        ulonglong2 xrp = *(const ulonglong2*)&xr[(size_t)node * 128 + ch];
        u64 acc0 = 0ull, acc1 = 0ull;
        float denom = 0.f;

        // prefetched indices for the current iteration
        int cidx[4];
#pragma unroll
        for (int j = 0; j < 4; j++) cidx[j] = __ldg(&csr_src[min(s + j, e - 1)]);

        for (int i = s; i < e; i += 4) {
            // prefetch next iteration's indices (clamped; cheap, 4 regs)
            int nidx[4];
#pragma unroll
            for (int j = 0; j < 4; j++)
                nidx[j] = __ldg(&csr_src[min(i + 4 + j, e - 1)]);

            int pidx[4];
#pragma unroll
            for (int j = 0; j < 4; j++) pidx[j] = min(i + j, e - 1);
            ulonglong2 xlv[4];
#pragma unroll
            for (int j = 0; j < 4; j++)
                xlv[j] = *(const ulonglong2*)&xl[(size_t)cidx[j] * 128 + ch];

            u64 m0[4], m1[4];
#pragma unroll
            for (int j = 0; j < 4; j++) {
                m0[j] = fadd2(xlv[j].x, xrp.x);
                m1[j] = fadd2(xlv[j].y, xrp.y);
            }

#pragma unroll
            for (int kk = 0; kk < 4; kk++) {
                float4 ea[4];
#pragma unroll
                for (int j = 0; j < 4; j++)
                    ea[j] = *(const float4*)&eattr[(size_t)pidx[j] * FEE + kk * 4];
#pragma unroll
                for (int r = 0; r < 4; r++) {
                    ulonglong2 w = *(const ulonglong2*)&sWe[4 * kk + r][ch];
#pragma unroll
                    for (int j = 0; j < 4; j++) {
                        float ev = (r == 0) ? ea[j].x : (r == 1) ? ea[j].y
                                 : (r == 2) ? ea[j].z : ea[j].w;
                        u64 sv = splat2(ev);
                        m0[j] = ffma2(sv, w.x, m0[j]);
                        m1[j] = ffma2(sv, w.y, m1[j]);
                    }
                }
            }

            float pv[4];
#pragma unroll
            for (int j = 0; j < 4; j++) {
                float2 f0 = unpack2(m0[j]), f1 = unpack2(m1[j]);
                pv[j] = fmaxf(f0.x, NEG_SLOPE * f0.x) * att4.x
                      + fmaxf(f0.y, NEG_SLOPE * f0.y) * att4.y
                      + fmaxf(f1.x, NEG_SLOPE * f1.x) * att4.z
                      + fmaxf(f1.y, NEG_SLOPE * f1.y) * att4.w;
            }
#pragma unroll
            for (int o = 1; o <= 4; o <<= 1) {
#pragma unroll
                for (int j = 0; j < 4; j++)
                    pv[j] += __shfl_xor_sync(0xffffffffu, pv[j], o);
            }
#pragma unroll
            for (int j = 0; j < 4; j++) {
                float ex = __expf(pv[j]);
                if (i + j < e) {            // warp-uniform predicate
                    denom += ex;
                    u64 e2 = splat2(ex);
                    acc0 = ffma2(e2, xlv[j].x, acc0);
                    acc1 = ffma2(e2, xlv[j].y, acc1);
                }
            }
#pragma unroll
            for (int j = 0; j < 4; j++) cidx[j] = nidx[j];
        }

        float inv = 1.f / (denom + 1e-16f);
        float2 a0 = unpack2(acc0), a1 = unpack2(acc1);
        float ox = a0.x * inv + b4.x;
        float oy = a0.y * inv + b4.y;
        float oz = a1.x * inv + b4.z;
        float ow = a1.y * inv + b4.w;
        float4 o;
        o.x = (ox > 0.f) ? ox : expm1f(ox);
        o.y = (oy > 0.f) ? oy : expm1f(oy);
        o.z = (oz > 0.f) ? oz : expm1f(oz);
        o.w = (ow > 0.f) ? ow : expm1f(ow);
        *(float4*)&out[(size_t)node * 128 + ch] = o;
    }
}

// ---------------- batch pooling ----------------
__global__ __launch_bounds__(128) void pool_kernel(
    const float* __restrict__ h, const int* __restrict__ batch,
    float* __restrict__ gsum, unsigned* __restrict__ gmax, int* __restrict__ gcnt,
    int n_nodes)
{
    __shared__ float    ssum[BBB][HIDD];
    __shared__ unsigned smax[BBB][HIDD];
    __shared__ int      scnt[BBB];
    int tid = threadIdx.x;
#pragma unroll
    for (int b = 0; b < BBB; b++) { ssum[b][tid] = 0.f; smax[b][tid] = 0u; }
    if (tid < BBB) scnt[tid] = 0;
    __syncthreads();
    int chunk = (n_nodes + gridDim.x - 1) / gridDim.x;
    int st = blockIdx.x * chunk;
    int en = min(st + chunk, n_nodes);
    for (int n = st; n < en; n++) {
        int b = __ldg(&batch[n]);
        float v = h[(size_t)n * 128 + tid];
        ssum[b][tid] += v;
        unsigned ev = enc_ord(v);
        if (ev > smax[b][tid]) smax[b][tid] = ev;
        if (tid == 0) scnt[b]++;
    }
    __syncthreads();
#pragma unroll
    for (int b = 0; b < BBB; b++) {
        atomicAdd(&gsum[b * HIDD + tid], ssum[b][tid]);
        atomicMax(&gmax[b * HIDD + tid], smax[b][tid]);
    }
    if (tid < BBB) atomicAdd(&gcnt[tid], scnt[tid]);
}

// ---------------- FC head ----------------
__global__ __launch_bounds__(128) void fc_kernel(
    const float* __restrict__ gsum, const unsigned* __restrict__ gmax,
    const int* __restrict__ gcnt,
    const float* __restrict__ Wf1, const float* __restrict__ bf1,
    const float* __restrict__ Wf2, const float* __restrict__ bf2,
    float* __restrict__ out)
{
    __shared__ float comb[512];
    __shared__ float hid[128];
    int b = blockIdx.x;
    int tid = threadIdx.x;
#pragma unroll
    for (int g = 0; g < 2; g++) {
        int cnt = gcnt[g * BBB + b];
        float invc = 1.f / (float)max(cnt, 1);
        float mean = gsum[(size_t)(g * BBB + b) * HIDD + tid] * invc;
        unsigned mu = gmax[(size_t)(g * BBB + b) * HIDD + tid];
        float mx = (cnt > 0) ? dec_ord(mu) : 0.f;
        comb[g * 256 + tid]       = mean;
        comb[g * 256 + 128 + tid] = mx;
    }
    __syncthreads();
    float a = bf1[tid];
#pragma unroll 8
    for (int i = 0; i < 512; i++) a += comb[i] * Wf1[(size_t)i * 128 + tid];
    hid[tid] = fmaxf(a, 0.f);
    __syncthreads();
    if (tid < 32) {
        float s = 0.f;
        for (int j = tid; j < 128; j += 32) s += hid[j] * Wf2[j];
        s += __shfl_xor_sync(0xffffffffu, s, 1);
        s += __shfl_xor_sync(0xffffffffu, s, 2);
        s += __shfl_xor_sync(0xffffffffu, s, 4);
        s += __shfl_xor_sync(0xffffffffu, s, 8);
        s += __shfl_xor_sync(0xffffffffu, s, 16);
        if (tid == 0) out[b] = 1.f / (1.f + __expf(-(s + bf2[0])));
    }
}

// ---------------- launch ----------------
extern "C" void kernel_launch(void* const* d_in, const int* in_sizes, int n_in,
                              void* d_out, int out_size)
{
    (void)n_in; (void)out_size;
    int n = in_sizes[3];
    int E = in_sizes[1] / 2;

    static cudaStream_t s2 = 0;
    static cudaEvent_t evF = 0, evJ = 0;
    if (!s2) {
        cudaStreamCreateWithFlags(&s2, cudaStreamNonBlocking);
        cudaEventCreateWithFlags(&evF, cudaEventDisableTiming);
        cudaEventCreateWithFlags(&evJ, cudaEventDisableTiming);
    }

    void* p;
    float *xl, *xr, *h, *h2, *eattr, *psum;
    int *deg, *off, *cur, *srcb, *pcnt, *bsums;
    unsigned *pmax;
    cudaGetSymbolAddress(&p, g_xl);     xl    = (float*)p;
    cudaGetSymbolAddress(&p, g_xr);     xr    = (float*)p;
    cudaGetSymbolAddress(&p, g_h);      h     = (float*)p;
    cudaGetSymbolAddress(&p, g_h2);     h2    = (float*)p;
    cudaGetSymbolAddress(&p, g_deg);    deg   = (int*)p;
    cudaGetSymbolAddress(&p, g_off);    off   = (int*)p;
    cudaGetSymbolAddress(&p, g_cur);    cur   = (int*)p;
    cudaGetSymbolAddress(&p, g_srcidx); srcb  = (int*)p;
    cudaGetSymbolAddress(&p, g_eattr);  eattr = (float*)p;
    cudaGetSymbolAddress(&p, g_bsums);  bsums = (int*)p;
    cudaGetSymbolAddress(&p, g_psum);   psum  = (float*)p;
    cudaGetSymbolAddress(&p, g_pmax);   pmax  = (unsigned*)p;
    cudaGetSymbolAddress(&p, g_pcnt);   pcnt  = (int*)p;

    const float* W1l  = (const float*)d_in[8];
    const float* b1l  = (const float*)d_in[9];
    const float* W1r  = (const float*)d_in[10];
    const float* b1r  = (const float*)d_in[11];
    const float* W1e  = (const float*)d_in[12];
    const float* att1 = (const float*)d_in[13];
    const float* bias1= (const float*)d_in[14];
    const float* W2l  = (const float*)d_in[15];
    const float* b2l  = (const float*)d_in[16];
    const float* W2r  = (const float*)d_in[17];
    const float* b2r  = (const float*)d_in[18];
    const float* W2e  = (const float*)d_in[19];
    const float* att2 = (const float*)d_in[20];
    const float* bias2= (const float*)d_in[21];
    const float* Wf1  = (const float*)d_in[22];
    const float* bf1  = (const float*)d_in[23];
    const float* Wf2  = (const float*)d_in[24];
    const float* bf2  = (const float*)d_in[25];

    cudaMemsetAsync(psum, 0, 2 * BBB * HIDD * sizeof(float), 0);
    cudaMemsetAsync(pmax, 0, 2 * BBB * HIDD * sizeof(unsigned), 0);
    cudaMemsetAsync(pcnt, 0, 2 * BBB * sizeof(int), 0);

    cudaEventRecord(evF, 0);
    cudaStreamWaitEvent(s2, evF, 0);

    dim3 ggrid(4, (n + 127) / 128);
    int eblocks = (E + 255) / 256;
    int nb1024 = (n + 1023) / 1024;
    int edge_blocks = 1184;

    for (int g = 0; g < 2; g++) {
        cudaStream_t st = (g == 0) ? (cudaStream_t)0 : s2;
        const float* x     = (const float*)d_in[g * 4 + 0];
        const int*   ei    = (const int*)  d_in[g * 4 + 1];
        const float* ea    = (const float*)d_in[g * 4 + 2];
        const int*   batch = (const int*)  d_in[g * 4 + 3];
        float* xl_g    = xl    + (size_t)g * NN * HIDD;
        float* xr_g    = xr    + (size_t)g * NN * HIDD;
        float* h_g     = h     + (size_t)g * NN * HIDD;
        float* h2_g    = h2    + (size_t)g * NN * HIDD;
        int*   deg_g   = deg   + (size_t)g * NN;
        int*   off_g   = off   + (size_t)g * (NN + 1);
        int*   cur_g   = cur   + (size_t)g * NN;
        int*   src_g   = srcb  + (size_t)g * EE;
        float* eattr_g = eattr + (size_t)g * EE * FEE;
        int*   bs_g    = bsums + (size_t)g * 1024;

        cudaMemsetAsync(deg_g, 0, n * sizeof(int), st);
        count_kernel<<<eblocks, 256, 0, st>>>(ei, deg_g, E);
        partial_kernel<<<nb1024, 1024, 0, st>>>(deg_g, bs_g, n);
        scan_bsums_kernel<<<1, 1024, 0, st>>>(bs_g, nb1024, off_g, n);
        write_off_kernel<<<nb1024, 1024, 0, st>>>(deg_g, bs_g, off_g, cur_g, n);
        scatter_kernel<<<eblocks, 256, 0, st>>>(ei, ea, cur_g, src_g, eattr_g, E);

        gemm_tc_kernel<<<ggrid, 256, 0, st>>>(x, W1l, b1l, xl_g, W1r, b1r, xr_g, n);
        edge_kernel<<<edge_blocks, 128, 0, st>>>(xl_g, xr_g, eattr_g, src_g, off_g,
                                                 W1e, att1, bias1, h_g, n);
        gemm_tc_kernel<<<ggrid, 256, 0, st>>>(h_g, W2l, b2l, xl_g, W2r, b2r, xr_g, n);
        edge_kernel<<<edge_blocks, 128, 0, st>>>(xl_g, xr_g, eattr_g, src_g, off_g,
                                                 W2e, att2, bias2, h2_g, n);
        pool_kernel<<<200, 128, 0, st>>>(h2_g, batch, psum + g * BBB * HIDD,
                                         pmax + g * BBB * HIDD, pcnt + g * BBB, n);
    }

    cudaEventRecord(evJ, s2);
    cudaStreamWaitEvent((cudaStream_t)0, evJ, 0);

    fc_kernel<<<BBB, 128>>>(psum, pmax, pcnt, Wf1, bf1, Wf2, bf2, (float*)d_out);
}